// round 4
// baseline (speedup 1.0000x reference)
#include <cuda_runtime.h>
#include <cuda_bf16.h>
#include <cstdint>

// GriddingDistance round 4: bin-by-x-slab, then ownership accumulation.
// Output is written exactly once (no memset, no global atomics on the grid).
//
//  K0 zero_meta:  reset bin cursors + overflow counter
//  K1 bin_kernel: bucket interior points into (cloud,sample,x0) bins,
//                 record = (shifted py, pz, dx); non-interior / cap-overflow
//                 points go to an overflow list
//  K2 accum_kernel: one block per x-slab; SMEM 128x128 accumulator; reads
//                 bins s (w=1-dx) and s-1 (w=dx); writes 64KB slab coalesced
//  K3 overflow_kernel: clamped 8-corner global-atomic fallback (empty here)

#define R      128
#define RR     16384            // R*R
#define GSZ    2097152          // R^3
#define MAXB   8
#define NBINS  (2 * MAXB * R)   // 2048
#define CAP    1024
#define OVCAP  65536

__device__ int    g_cursor[NBINS];
__device__ int    g_ovCount;
__device__ int    g_ovList[OVCAP];
__device__ float2 g_recYZ[NBINS * CAP];   // 16 MB
__device__ float  g_recD [NBINS * CAP];   //  8 MB

__global__ void zero_meta()
{
    int t = blockIdx.x * blockDim.x + threadIdx.x;
    if (t < NBINS) g_cursor[t] = 0;
    if (t == 0)    g_ovCount  = 0;
}

__global__ __launch_bounds__(1024)
void bin_kernel(const float* __restrict__ pred, const float* __restrict__ gt,
                int n_per_sample, int total_points, int b)
{
    __shared__ int lCount[R];
    __shared__ int lBase[R];

    int tid   = threadIdx.x;
    int cloud = blockIdx.y;
    const float* __restrict__ pts = cloud ? gt : pred;
    int t = blockIdx.x * blockDim.x + tid;

    if (tid < R) lCount[tid] = 0;
    __syncthreads();

    int blockSample = (int)(((long long)blockIdx.x * blockDim.x) / n_per_sample);

    bool valid = (t < total_points);
    float py = 0.f, pz = 0.f, dx = 0.f;
    int ix = 0;
    bool good = false;
    if (valid) {
        float px = fmaf(pts[3 * t + 0], 128.0f, 64.0f);
        py       = fmaf(pts[3 * t + 1], 128.0f, 64.0f);
        pz       = fmaf(pts[3 * t + 2], 128.0f, 64.0f);
        float fx = floorf(px), fy = floorf(py), fz = floorf(pz);
        ix = (int)fx;
        int iy = (int)fy, iz = (int)fz;
        dx = px - fx;
        bool interior = (ix >= 0) & (ix + 1 < R) &
                        (iy >= 0) & (iy + 1 < R) &
                        (iz >= 0) & (iz + 1 < R);
        bool sameSample = (t / n_per_sample) == blockSample;
        good = interior & sameSample;
    }

    int rank = 0;
    if (good) rank = atomicAdd(&lCount[ix], 1);
    __syncthreads();

    if (tid < R && lCount[tid] > 0) {
        int bin = (cloud * b + blockSample) * R + tid;
        lBase[tid] = atomicAdd(&g_cursor[bin], lCount[tid]);
    }
    __syncthreads();

    if (good) {
        int pos = lBase[ix] + rank;
        if (pos < CAP) {
            int bin = (cloud * b + blockSample) * R + ix;
            int idx = bin * CAP + pos;
            g_recYZ[idx] = make_float2(py, pz);
            g_recD[idx]  = dx;
        } else {
            good = false;   // bin full -> overflow fallback
        }
    }
    if (valid && !good) {
        int o = atomicAdd(&g_ovCount, 1);
        if (o < OVCAP) g_ovList[o] = (cloud << 30) | t;
    }
}

__global__ __launch_bounds__(512)
void accum_kernel(float* __restrict__ out, int b, long long grid_per_cloud)
{
    extern __shared__ float acc[];   // RR floats = 64 KB

    int tid    = threadIdx.x;
    int blk    = blockIdx.x;         // 0 .. 2*b*R-1
    int slab   = blk & (R - 1);
    int cs     = blk >> 7;
    int cloud  = cs / b;
    int sample = cs - cloud * b;

    float4* acc4 = (float4*)acc;
    for (int i = tid; i < RR / 4; i += blockDim.x)
        acc4[i] = make_float4(0.f, 0.f, 0.f, 0.f);
    __syncthreads();

    int binbase = (cloud * b + sample) * R;

    #pragma unroll
    for (int side = 0; side < 2; side++) {
        int bx = slab - side;        // side 0: own bin (w=1-dx); side 1: left bin (w=dx)
        if (bx < 0) continue;
        int bin = binbase + bx;
        int cnt = min(g_cursor[bin], CAP);
        for (int i = tid; i < cnt; i += blockDim.x) {
            int idx   = bin * CAP + i;
            float2 yz = g_recYZ[idx];
            float dxv = g_recD[idx];
            float wx  = side ? dxv : (1.0f - dxv);
            float fy = floorf(yz.x), fz = floorf(yz.y);
            float dy = yz.x - fy,    dz = yz.y - fz;
            int base = (int)fy * R + (int)fz;
            float wy0 = 1.0f - dy, wz0 = 1.0f - dz;
            atomicAdd(&acc[base        ], wx * wy0 * wz0);
            atomicAdd(&acc[base + 1    ], wx * wy0 * dz);
            atomicAdd(&acc[base + R    ], wx * dy  * wz0);
            atomicAdd(&acc[base + R + 1], wx * dy  * dz);
        }
    }
    __syncthreads();

    float* dst   = out + (long long)cloud * grid_per_cloud
                       + (long long)sample * GSZ + (long long)slab * RR;
    float4* dst4 = (float4*)dst;
    for (int i = tid; i < RR / 4; i += blockDim.x)
        dst4[i] = acc4[i];
}

__global__ __launch_bounds__(256)
void overflow_kernel(const float* __restrict__ pred, const float* __restrict__ gt,
                     float* __restrict__ out, int n_per_sample,
                     long long grid_per_cloud)
{
    int nov = min(g_ovCount, OVCAP);
    int stride = gridDim.x * blockDim.x;
    for (int i = blockIdx.x * blockDim.x + threadIdx.x; i < nov; i += stride) {
        int v     = g_ovList[i];
        int cloud = v >> 30;
        int t     = v & ((1 << 30) - 1);
        const float* __restrict__ pts = cloud ? gt : pred;
        float* __restrict__ gb = out + (long long)cloud * grid_per_cloud
                                     + (long long)(t / n_per_sample) * GSZ;

        float px = fmaf(pts[3 * t + 0], 128.0f, 64.0f);
        float py = fmaf(pts[3 * t + 1], 128.0f, 64.0f);
        float pz = fmaf(pts[3 * t + 2], 128.0f, 64.0f);
        float fx = floorf(px), fy = floorf(py), fz = floorf(pz);
        float dx = px - fx,   dy = py - fy,   dz = pz - fz;
        int ix = (int)fx, iy = (int)fy, iz = (int)fz;

        int ix0 = min(max(ix,     0), R - 1), ix1 = min(max(ix + 1, 0), R - 1);
        int iy0 = min(max(iy,     0), R - 1), iy1 = min(max(iy + 1, 0), R - 1);
        int iz0 = min(max(iz,     0), R - 1), iz1 = min(max(iz + 1, 0), R - 1);
        int rx0 = ix0 * RR, rx1 = ix1 * RR;
        int ry0 = iy0 * R,  ry1 = iy1 * R;
        float wx0 = 1.f - dx, wy0 = 1.f - dy, wz0 = 1.f - dz;
        float w00 = wx0 * wy0, w01 = wx0 * dy, w10 = dx * wy0, w11 = dx * dy;

        atomicAdd(gb + (rx0 + ry0 + iz0), w00 * wz0);
        atomicAdd(gb + (rx0 + ry0 + iz1), w00 * dz);
        atomicAdd(gb + (rx0 + ry1 + iz0), w01 * wz0);
        atomicAdd(gb + (rx0 + ry1 + iz1), w01 * dz);
        atomicAdd(gb + (rx1 + ry0 + iz0), w10 * wz0);
        atomicAdd(gb + (rx1 + ry0 + iz1), w10 * dz);
        atomicAdd(gb + (rx1 + ry1 + iz0), w11 * wz0);
        atomicAdd(gb + (rx1 + ry1 + iz1), w11 * dz);
    }
}

extern "C" void kernel_launch(void* const* d_in, const int* in_sizes, int n_in,
                              void* d_out, int out_size)
{
    const float* pred = (const float*)d_in[0];
    const float* gt   = (const float*)d_in[1];
    float* out = (float*)d_out;

    const int G = GSZ;
    int b = out_size / (2 * G);                        // 8
    int total_points = in_sizes[0] / 3;                // 524288
    int n = total_points / b;                          // 65536
    long long grid_per_cloud = (long long)b * G;

    static int smem_set = 0;
    if (!smem_set) {
        cudaFuncSetAttribute(accum_kernel,
                             cudaFuncAttributeMaxDynamicSharedMemorySize,
                             RR * sizeof(float));
        smem_set = 1;
    }

    zero_meta<<<2, 1024>>>();

    dim3 g1((total_points + 1023) / 1024, 2);
    bin_kernel<<<g1, 1024>>>(pred, gt, n, total_points, b);

    accum_kernel<<<2 * b * R, 512, RR * sizeof(float)>>>(out, b, grid_per_cloud);

    overflow_kernel<<<32, 256>>>(pred, gt, out, n, grid_per_cloud);
}

// round 5
// speedup vs baseline: 1.5643x; 1.5643x over previous
#include <cuda_runtime.h>
#include <cuda_bf16.h>
#include <cstdint>

// GriddingDistance round 5: round-3 phased structure (each cloud's 64MB grid
// L2-resident during its scatter) + widened z-window vector reductions:
//   iz even   -> red.v2 at iz          (4 ops/point)
//   iz%4 == 1 -> red.v4 at iz-1, lanes (0,wz0,wz1,0)   (4 ops/point)
//   iz%4 == 3 -> 8 scalar reds (straddles 16B windows)
// avg 5 lane-ops/point vs 6 in round 3.

#define GRID_R 128

__device__ __forceinline__ void red_add_f32(float* p, float v) {
    atomicAdd(p, v);  // return unused -> REDG
}

__device__ __forceinline__ void red_add_v2_f32(float* p, float a, float b) {
    asm volatile("red.global.add.v2.f32 [%0], {%1, %2};"
                 :: "l"(p), "f"(a), "f"(b) : "memory");
}

__device__ __forceinline__ void red_add_v4_f32(float* p, float a, float b,
                                               float c, float d) {
    asm volatile("red.global.add.v4.f32 [%0], {%1, %2, %3, %4};"
                 :: "l"(p), "f"(a), "f"(b), "f"(c), "f"(d) : "memory");
}

__device__ __forceinline__ void scatter_cloud(const float* __restrict__ pts,
                                              float* __restrict__ g,
                                              int n_per_sample,
                                              int total_points)
{
    int t = blockIdx.x * blockDim.x + threadIdx.x;
    if (t >= total_points) return;

    float px = fmaf(pts[3 * t + 0], 128.0f, 64.0f);
    float py = fmaf(pts[3 * t + 1], 128.0f, 64.0f);
    float pz = fmaf(pts[3 * t + 2], 128.0f, 64.0f);

    float fx = floorf(px), fy = floorf(py), fz = floorf(pz);
    float dx = px - fx,   dy = py - fy,   dz = pz - fz;

    int ix = (int)fx, iy = (int)fy, iz = (int)fz;

    float wx0 = 1.0f - dx, wy0 = 1.0f - dy, wz0 = 1.0f - dz;
    float w00 = wx0 * wy0;
    float w01 = wx0 * dy;
    float w10 = dx  * wy0;
    float w11 = dx  * dy;

    int sample = t / n_per_sample;
    float* __restrict__ gb = g + (long long)sample * (GRID_R * GRID_R * GRID_R);

    bool interior = (ix >= 0) & (ix + 1 < GRID_R) &
                    (iy >= 0) & (iy + 1 < GRID_R) &
                    (iz >= 0) & (iz + 1 < GRID_R);

    if (interior) {
        int r00 = (ix * GRID_R + iy) * GRID_R + iz;
        int r01 = r00 + GRID_R;
        int r10 = r00 + GRID_R * GRID_R;
        int r11 = r10 + GRID_R;

        int m4 = iz & 3;
        if ((m4 & 1) == 0) {
            // iz even: aligned 8B pair
            red_add_v2_f32(gb + r00, w00 * wz0, w00 * dz);
            red_add_v2_f32(gb + r01, w01 * wz0, w01 * dz);
            red_add_v2_f32(gb + r10, w10 * wz0, w10 * dz);
            red_add_v2_f32(gb + r11, w11 * wz0, w11 * dz);
        } else if (m4 == 1) {
            // iz%4==1: corners at window offsets 1,2 of 16B-aligned (iz-1)
            red_add_v4_f32(gb + r00 - 1, 0.f, w00 * wz0, w00 * dz, 0.f);
            red_add_v4_f32(gb + r01 - 1, 0.f, w01 * wz0, w01 * dz, 0.f);
            red_add_v4_f32(gb + r10 - 1, 0.f, w10 * wz0, w10 * dz, 0.f);
            red_add_v4_f32(gb + r11 - 1, 0.f, w11 * wz0, w11 * dz, 0.f);
        } else {
            // iz%4==3: straddles two 16B windows -> scalar
            red_add_f32(gb + r00,     w00 * wz0);
            red_add_f32(gb + r00 + 1, w00 * dz);
            red_add_f32(gb + r01,     w01 * wz0);
            red_add_f32(gb + r01 + 1, w01 * dz);
            red_add_f32(gb + r10,     w10 * wz0);
            red_add_f32(gb + r10 + 1, w10 * dz);
            red_add_f32(gb + r11,     w11 * wz0);
            red_add_f32(gb + r11 + 1, w11 * dz);
        }
    } else {
        // general clamped path (matches reference jnp.clip semantics)
        int ix0 = min(max(ix,     0), GRID_R - 1);
        int ix1 = min(max(ix + 1, 0), GRID_R - 1);
        int iy0 = min(max(iy,     0), GRID_R - 1);
        int iy1 = min(max(iy + 1, 0), GRID_R - 1);
        int iz0 = min(max(iz,     0), GRID_R - 1);
        int iz1 = min(max(iz + 1, 0), GRID_R - 1);
        int rx0 = ix0 * GRID_R * GRID_R, rx1 = ix1 * GRID_R * GRID_R;
        int ry0 = iy0 * GRID_R,          ry1 = iy1 * GRID_R;
        red_add_f32(gb + (rx0 + ry0 + iz0), w00 * wz0);
        red_add_f32(gb + (rx0 + ry0 + iz1), w00 * dz);
        red_add_f32(gb + (rx0 + ry1 + iz0), w01 * wz0);
        red_add_f32(gb + (rx0 + ry1 + iz1), w01 * dz);
        red_add_f32(gb + (rx1 + ry0 + iz0), w10 * wz0);
        red_add_f32(gb + (rx1 + ry0 + iz1), w10 * dz);
        red_add_f32(gb + (rx1 + ry1 + iz0), w11 * wz0);
        red_add_f32(gb + (rx1 + ry1 + iz1), w11 * dz);
    }
}

// Phase 2: blocks y==0 scatter pred; blocks y==1 zero the gt grid half.
__global__ __launch_bounds__(256)
void scatter_pred_zero_gt_kernel(const float* __restrict__ pred,
                                 float* __restrict__ out,
                                 int n_per_sample,
                                 int total_points,
                                 long long grid_per_cloud)
{
    if (blockIdx.y == 0) {
        scatter_cloud(pred, out, n_per_sample, total_points);
    } else {
        float4* __restrict__ z = (float4*)(out + grid_per_cloud);
        long long n4 = grid_per_cloud >> 2;
        long long nthreads = (long long)gridDim.x * blockDim.x;
        long long t = (long long)blockIdx.x * blockDim.x + threadIdx.x;
        float4 zero = make_float4(0.f, 0.f, 0.f, 0.f);
        for (long long i = t; i < n4; i += nthreads)
            z[i] = zero;
    }
}

__global__ __launch_bounds__(256)
void scatter_gt_kernel(const float* __restrict__ gt,
                       float* __restrict__ out,
                       int n_per_sample,
                       int total_points,
                       long long grid_per_cloud)
{
    scatter_cloud(gt, out + grid_per_cloud, n_per_sample, total_points);
}

extern "C" void kernel_launch(void* const* d_in, const int* in_sizes, int n_in,
                              void* d_out, int out_size)
{
    const float* pred = (const float*)d_in[0];
    const float* gt   = (const float*)d_in[1];
    float* out = (float*)d_out;

    const int G = GRID_R * GRID_R * GRID_R;            // 2097152
    int b = out_size / (2 * G);                        // 8
    int total_points = in_sizes[0] / 3;                // 524288
    int n = total_points / b;                          // 65536
    long long grid_per_cloud = (long long)b * G;       // 16777216 floats

    // Phase 1: zero pred half only (lands in L2, stays resident for phase 2)
    cudaMemsetAsync(d_out, 0, (size_t)grid_per_cloud * sizeof(float));

    int nblk = (total_points + 255) / 256;             // 2048

    // Phase 2: scatter pred (L2-resident grid) + zero gt half concurrently
    dim3 grid2(nblk, 2);
    scatter_pred_zero_gt_kernel<<<grid2, 256>>>(pred, out, n, total_points,
                                                grid_per_cloud);

    // Phase 3: scatter gt (its grid now L2-resident from phase 2 zeroing)
    scatter_gt_kernel<<<nblk, 256>>>(gt, out, n, total_points, grid_per_cloud);
}